// round 15
// baseline (speedup 1.0000x reference)
#include <cuda_runtime.h>
#include <math.h>

#define NN   50000
#define NE   800000
#define HIDC 128
#define NOUT 32

// ---------------- scratch (device globals; no allocation allowed) ----------------
__device__ __align__(16) float g_h   [NN * HIDC];   // hs = (x@W)*dis[row]
__device__ __align__(16) float g_agg [NN * HIDC];   // aggregated pre-BN
__device__ __align__(16) float g_x   [NN * HIDC];   // running features (post residual)
__device__ __align__(16) float g_h2  [NN * NOUT];   // final-layer hs
__device__ __align__(16) float g_dis [NN];
__device__ int   g_deg   [NN];
__device__ int   g_rowptr[NN + 1];
__device__ int   g_cnt   [NN];
__device__ int   g_col   [NE];
__device__ int   g_is64;
__device__ __align__(16) float g_bnsum[2 * HIDC];   // per-layer BN sum
__device__ __align__(16) float g_bnsq [2 * HIDC];   // per-layer BN sum-of-squares

// ---------------- dtype detection for edge_index (int32 vs int64) ----------------
__global__ void k_detect(const unsigned int* __restrict__ w) {
    __shared__ int any_nz;
    if (threadIdx.x == 0) any_nz = 0;
    __syncthreads();
    unsigned int v = w[2 * threadIdx.x + 1];   // tid in [0,1024)
    if (v != 0u) atomicOr(&any_nz, 1);
    __syncthreads();
    if (threadIdx.x == 0) g_is64 = any_nz ? 0 : 1;
}

__device__ __forceinline__ int load_edge(const void* ei, long long idx) {
    if (g_is64) return (int)((const long long*)ei)[idx];
    return ((const int*)ei)[idx];
}

// ---------------- setup kernels ----------------
// zero degree + both layers' BN accumulators (must re-zero every launch)
__global__ void k_zero() {
    int i = blockIdx.x * blockDim.x + threadIdx.x;
    if (i < NN) g_deg[i] = 0;
    if (i < 2 * HIDC) { g_bnsum[i] = 0.f; g_bnsq[i] = 0.f; }
}
__global__ void k_deg(const void* __restrict__ ei) {
    int e = blockIdx.x * blockDim.x + threadIdx.x;
    if (e < NE) {
        int d = load_edge(ei, (long long)NE + e);
        if ((unsigned)d < (unsigned)NN)
            atomicAdd(&g_deg[d], 1);
    }
}
// single-block exclusive scan of g_deg -> g_rowptr (+ g_cnt copy + g_dis)
__global__ void k_scan() {
    __shared__ int tsum[1024];
    int tid = threadIdx.x;
    const int CH = (NN + 1023) / 1024;   // 49
    int base = tid * CH;
    int s = 0;
    for (int i = 0; i < CH; i++) {
        int idx = base + i;
        if (idx < NN) {
            int d = g_deg[idx];
            s += d;
            g_dis[idx] = rsqrtf((float)d + 1.0f);
        }
    }
    tsum[tid] = s;
    __syncthreads();
    for (int off = 1; off < 1024; off <<= 1) {
        int v = tsum[tid];
        int add = (tid >= off) ? tsum[tid - off] : 0;
        __syncthreads();
        tsum[tid] = v + add;
        __syncthreads();
    }
    int run = (tid == 0) ? 0 : tsum[tid - 1];
    for (int i = 0; i < CH; i++) {
        int idx = base + i;
        if (idx < NN) {
            g_rowptr[idx] = run;
            g_cnt[idx]    = run;
            run += g_deg[idx];
        }
    }
    if (tid == 1023) g_rowptr[NN] = tsum[1023];
}
__global__ void k_fill(const void* __restrict__ ei) {
    int e = blockIdx.x * blockDim.x + threadIdx.x;
    if (e < NE) {
        int s = load_edge(ei, e);
        int d = load_edge(ei, (long long)NE + e);
        if ((unsigned)s < (unsigned)NN && (unsigned)d < (unsigned)NN) {
            int pos = atomicAdd(&g_cnt[d], 1);
            if ((unsigned)pos < (unsigned)NE) g_col[pos] = s;
        }
    }
}

// ---------------- GEMM 128x128: g_h[row][c] = (SRC[row] . W[:,c]) * dis[row] ----------------
// 128 threads/block, tile 64 rows x 128 cols, micro-tile 8x8 per thread.
// Two 64-wide K chunks; static shared exactly 48KB.
__global__ void __launch_bounds__(128) k_gemm128(const float* __restrict__ X,
                                                 const float* __restrict__ W,
                                                 int use_gx) {
    __shared__ float Ws[64][HIDC];   // 32KB
    __shared__ float Xs[64][64];     // 16KB
    const float* src = use_gx ? (const float*)g_x : X;

    int tid  = threadIdx.x;
    int row0 = blockIdx.x * 64;
    int cg = tid & 15;   // cols cg*8 .. cg*8+7
    int rg = tid >> 4;   // rows rg*8 .. rg*8+7

    float4 a0[8], a1[8];
#pragma unroll
    for (int r = 0; r < 8; r++) {
        a0[r] = make_float4(0.f, 0.f, 0.f, 0.f);
        a1[r] = make_float4(0.f, 0.f, 0.f, 0.f);
    }

#pragma unroll 1
    for (int kc = 0; kc < 2; kc++) {
        const float* Wsrc = W + kc * 64 * HIDC;
        for (int i = tid * 4; i < 64 * HIDC; i += 128 * 4)
            *(float4*)(&Ws[0][0] + i) = *(const float4*)(Wsrc + i);
        for (int i = tid; i < 64 * 16; i += 128) {
            int r  = i >> 4;
            int kg = (i & 15) * 4;
            int row = row0 + r;
            float4 v = make_float4(0.f, 0.f, 0.f, 0.f);
            if (row < NN) v = *(const float4*)&src[(size_t)row * HIDC + kc * 64 + kg];
            *(float4*)&Xs[r][kg] = v;
        }
        __syncthreads();

        for (int k = 0; k < 64; k += 4) {
            float4 xv[8];
#pragma unroll
            for (int r = 0; r < 8; r++)
                xv[r] = *(float4*)&Xs[rg * 8 + r][k];
#pragma unroll
            for (int kk = 0; kk < 4; kk++) {
                float4 w0 = *(float4*)&Ws[k + kk][cg * 8];
                float4 w1 = *(float4*)&Ws[k + kk][cg * 8 + 4];
#pragma unroll
                for (int r = 0; r < 8; r++) {
                    float xs = (kk == 0) ? xv[r].x : (kk == 1) ? xv[r].y
                             : (kk == 2) ? xv[r].z : xv[r].w;
                    a0[r].x = fmaf(xs, w0.x, a0[r].x);
                    a0[r].y = fmaf(xs, w0.y, a0[r].y);
                    a0[r].z = fmaf(xs, w0.z, a0[r].z);
                    a0[r].w = fmaf(xs, w0.w, a0[r].w);
                    a1[r].x = fmaf(xs, w1.x, a1[r].x);
                    a1[r].y = fmaf(xs, w1.y, a1[r].y);
                    a1[r].z = fmaf(xs, w1.z, a1[r].z);
                    a1[r].w = fmaf(xs, w1.w, a1[r].w);
                }
            }
        }
        __syncthreads();
    }

#pragma unroll
    for (int r = 0; r < 8; r++) {
        int row = row0 + rg * 8 + r;
        if (row < NN) {
            float d = g_dis[row];
            float4 o0 = make_float4(a0[r].x * d, a0[r].y * d, a0[r].z * d, a0[r].w * d);
            float4 o1 = make_float4(a1[r].x * d, a1[r].y * d, a1[r].z * d, a1[r].w * d);
            *(float4*)&g_h[(size_t)row * HIDC + cg * 8]     = o0;
            *(float4*)&g_h[(size_t)row * HIDC + cg * 8 + 4] = o1;
        }
    }
}

// ---------------- GEMM 128x32 (final layer): g_h2 = (g_x @ W2) * dis ----------------
__global__ void __launch_bounds__(256) k_gemm32(const float* __restrict__ W2) {
    __shared__ float Ws[HIDC * NOUT];  // 16KB
    int tid = threadIdx.x;
    for (int i = tid * 4; i < HIDC * NOUT; i += 256 * 4)
        *(float4*)&Ws[i] = *(const float4*)&W2[i];
    __syncthreads();

    int lane = tid & 31, w = tid >> 5;
    int row = blockIdx.x * 8 + w;
    if (row >= NN) return;
    const float* xr = g_x + (size_t)row * HIDC;
    float acc = 0.f;
#pragma unroll
    for (int k = 0; k < HIDC; k += 4) {
        float4 x4 = *(const float4*)&xr[k];  // uniform across warp
        acc = fmaf(x4.x, Ws[(k + 0) * NOUT + lane], acc);
        acc = fmaf(x4.y, Ws[(k + 1) * NOUT + lane], acc);
        acc = fmaf(x4.z, Ws[(k + 2) * NOUT + lane], acc);
        acc = fmaf(x4.w, Ws[(k + 3) * NOUT + lane], acc);
    }
    g_h2[(size_t)row * NOUT + lane] = acc * g_dis[row];
}

// ---------------- CSR aggregation + fused BN partial reduction ----------------
// warp per node, float4 per lane; g_agg = dis*(self + neighbor sum) + b.
// Also accumulates per-channel sum / sum-of-squares into g_bnsum/g_bnsq[layer].
// NOTE: NN*32 == 1.6M threads == exactly 6250 blocks of 256 — no stragglers.
__global__ void __launch_bounds__(256) k_aggbn(const float* __restrict__ b, int layer) {
    __shared__ float s_sum[HIDC], s_sq[HIDC];
    int tid  = threadIdx.x;
    if (tid < HIDC) { s_sum[tid] = 0.f; s_sq[tid] = 0.f; }
    __syncthreads();

    int node = (blockIdx.x * 256 + tid) >> 5;
    int lane = tid & 31;
    const float4* hs4 = (const float4*)g_h;
    float4 acc = hs4[(size_t)node * 32 + lane];   // self term (hs already *dis[src])
    int e0 = g_rowptr[node], e1 = g_rowptr[node + 1];
    int e = e0;
    for (; e + 1 < e1; e += 2) {
        int s0 = g_col[e], s1 = g_col[e + 1];
        float4 v0 = hs4[(size_t)s0 * 32 + lane];
        float4 v1 = hs4[(size_t)s1 * 32 + lane];
        acc.x += v0.x + v1.x; acc.y += v0.y + v1.y;
        acc.z += v0.z + v1.z; acc.w += v0.w + v1.w;
    }
    if (e < e1) {
        int s = g_col[e];
        float4 v = hs4[(size_t)s * 32 + lane];
        acc.x += v.x; acc.y += v.y; acc.z += v.z; acc.w += v.w;
    }
    float d = g_dis[node];
    float4 bb = *(const float4*)&b[lane * 4];
    float4 o = make_float4(acc.x * d + bb.x, acc.y * d + bb.y,
                           acc.z * d + bb.z, acc.w * d + bb.w);
    ((float4*)g_agg)[(size_t)node * 32 + lane] = o;

    int c = lane * 4;
    atomicAdd(&s_sum[c + 0], o.x);  atomicAdd(&s_sq[c + 0], o.x * o.x);
    atomicAdd(&s_sum[c + 1], o.y);  atomicAdd(&s_sq[c + 1], o.y * o.y);
    atomicAdd(&s_sum[c + 2], o.z);  atomicAdd(&s_sq[c + 2], o.z * o.z);
    atomicAdd(&s_sum[c + 3], o.w);  atomicAdd(&s_sq[c + 3], o.w * o.w);
    __syncthreads();
    if (tid < HIDC) {
        atomicAdd(&g_bnsum[layer * HIDC + tid], s_sum[tid]);
        atomicAdd(&g_bnsq [layer * HIDC + tid], s_sq[tid]);
    }
}

// ---------------- BN apply (stats finalized per block) + ReLU + residual ----------------
// g_x = relu(g_agg*scale + shift) + (use_gx ? g_x : X)
__global__ void __launch_bounds__(256) k_bnapply(const float* __restrict__ X,
                                                 const float* __restrict__ g,
                                                 const float* __restrict__ be,
                                                 int layer, int use_gx) {
    __shared__ float s_scale[HIDC], s_shift[HIDC];
    int tid = threadIdx.x;
    if (tid < HIDC) {
        float mu  = g_bnsum[layer * HIDC + tid] * (1.0f / (float)NN);
        float var = g_bnsq [layer * HIDC + tid] * (1.0f / (float)NN) - mu * mu;
        float a = rsqrtf(var + 1e-5f) * g[tid];
        s_scale[tid] = a;
        s_shift[tid] = be[tid] - mu * a;
    }
    __syncthreads();

    int idx = blockIdx.x * 256 + tid;   // exactly NN*32 float4 groups
    const float4* xin = use_gx ? (const float4*)g_x : (const float4*)X;
    int cg = (idx & 31) * 4;
    float4 v  = ((const float4*)g_agg)[idx];
    float4 xi = xin[idx];
    float4 a  = *(float4*)&s_scale[cg];
    float4 sh = *(float4*)&s_shift[cg];
    float4 o;
    o.x = fmaxf(fmaf(v.x, a.x, sh.x), 0.f) + xi.x;
    o.y = fmaxf(fmaf(v.y, a.y, sh.y), 0.f) + xi.y;
    o.z = fmaxf(fmaf(v.z, a.z, sh.z), 0.f) + xi.z;
    o.w = fmaxf(fmaf(v.w, a.w, sh.w), 0.f) + xi.w;
    ((float4*)g_x)[idx] = o;
}

// ---------------- final aggregation + log_softmax (warp per node, lane = class) ----------------
__global__ void __launch_bounds__(256) k_aggout(const float* __restrict__ b2,
                                                float* __restrict__ OUT) {
    int node = (blockIdx.x * 256 + threadIdx.x) >> 5;
    int lane = threadIdx.x & 31;
    if (node >= NN) return;
    float acc = g_h2[(size_t)node * NOUT + lane];
    int e0 = g_rowptr[node], e1 = g_rowptr[node + 1];
    for (int e = e0; e < e1; e++) {
        int s = g_col[e];
        acc += g_h2[(size_t)s * NOUT + lane];
    }
    float z = acc * g_dis[node] + b2[lane];
    float m = z;
#pragma unroll
    for (int o = 16; o > 0; o >>= 1) m = fmaxf(m, __shfl_xor_sync(0xffffffffu, m, o));
    float ex = expf(z - m);
    float sm = ex;
#pragma unroll
    for (int o = 16; o > 0; o >>= 1) sm += __shfl_xor_sync(0xffffffffu, sm, o);
    OUT[(size_t)node * NOUT + lane] = z - m - logf(sm);
}

// ---------------- host launch: kernel launches ONLY ----------------
extern "C" void kernel_launch(void* const* d_in, const int* in_sizes, int n_in,
                              void* d_out, int out_size) {
    const float* x   = (const float*)d_in[0];
    const void*  ei  = d_in[1];
    const float* W0  = (const float*)d_in[2];
    const float* b0  = (const float*)d_in[3];
    const float* g0  = (const float*)d_in[4];
    const float* be0 = (const float*)d_in[5];
    const float* W1  = (const float*)d_in[6];
    const float* b1  = (const float*)d_in[7];
    const float* g1  = (const float*)d_in[8];
    const float* be1 = (const float*)d_in[9];
    const float* W2  = (const float*)d_in[10];
    const float* b2  = (const float*)d_in[11];
    float*       out = (float*)d_out;

    // ---- dtype detect + graph / degree / CSR build ----
    k_detect<<<1, 1024>>>((const unsigned int*)ei);
    k_zero<<<(NN + 255) / 256, 256>>>();
    k_deg<<<(NE + 255) / 256, 256>>>(ei);
    k_scan<<<1, 1024>>>();
    k_fill<<<(NE + 255) / 256, 256>>>(ei);

    const int GB = (NN + 63) / 64;        // gemm128 blocks (782)
    const int WB = (NN * 32) / 256;       // warp-per-node blocks (6250, exact)

    // ---- layer 0 ----
    k_gemm128<<<GB, 128>>>(x, W0, 0);
    k_aggbn<<<WB, 256>>>(b0, 0);
    k_bnapply<<<WB, 256>>>(x, g0, be0, 0, 0);

    // ---- layer 1 ----
    k_gemm128<<<GB, 128>>>(x, W1, 1);
    k_aggbn<<<WB, 256>>>(b1, 1);
    k_bnapply<<<WB, 256>>>(x, g1, be1, 1, 1);

    // ---- final layer + log_softmax ----
    k_gemm32<<<(NN + 7) / 8, 256>>>(W2);
    k_aggout<<<WB, 256>>>(b2, out);
}

// round 16
// speedup vs baseline: 1.3829x; 1.3829x over previous
#include <cuda_runtime.h>
#include <math.h>

#define NN   50000
#define NE   800000
#define HIDC 128
#define NOUT 32
#define NB   196   // ceil(NN/256) blocks for the scan phases

// ---------------- scratch (device globals; no allocation allowed) ----------------
__device__ __align__(16) float g_h   [NN * HIDC];   // hs = (x@W)*dis[row]
__device__ __align__(16) float g_agg [NN * HIDC];   // aggregated pre-BN
__device__ __align__(16) float g_x   [NN * HIDC];   // running features (post residual)
__device__ __align__(16) float g_h2  [NN * NOUT];   // final-layer hs
__device__ __align__(16) float g_dis [NN];
__device__ int   g_deg   [NN];
__device__ int   g_rowptr[NN + 1];
__device__ int   g_cnt   [NN];
__device__ int   g_col   [NE];
__device__ int   g_bsum  [NB];
__device__ int   g_boff  [NB];
__device__ int   g_is64;
__device__ __align__(16) float g_bnsum[2 * HIDC];   // per-layer BN sum
__device__ __align__(16) float g_bnsq [2 * HIDC];   // per-layer BN sum-of-squares

// ---------------- dtype detection for edge_index (int32 vs int64) ----------------
__global__ void k_detect(const unsigned int* __restrict__ w) {
    __shared__ int any_nz;
    if (threadIdx.x == 0) any_nz = 0;
    __syncthreads();
    unsigned int v = w[2 * threadIdx.x + 1];   // tid in [0,1024)
    if (v != 0u) atomicOr(&any_nz, 1);
    __syncthreads();
    if (threadIdx.x == 0) g_is64 = any_nz ? 0 : 1;
}

__device__ __forceinline__ int load_edge(const void* ei, long long idx) {
    if (g_is64) return (int)((const long long*)ei)[idx];
    return ((const int*)ei)[idx];
}

// ---------------- setup kernels ----------------
// zero degree + both layers' BN accumulators (must re-zero every launch)
__global__ void k_zero() {
    int i = blockIdx.x * blockDim.x + threadIdx.x;
    if (i < NN) g_deg[i] = 0;
    if (i < 2 * HIDC) { g_bnsum[i] = 0.f; g_bnsq[i] = 0.f; }
}
__global__ void k_deg(const void* __restrict__ ei) {
    int e = blockIdx.x * blockDim.x + threadIdx.x;
    if (e < NE) {
        int d = load_edge(ei, (long long)NE + e);
        if ((unsigned)d < (unsigned)NN)
            atomicAdd(&g_deg[d], 1);
    }
}

// ---- multi-block exclusive scan of g_deg -> g_rowptr (3 phases) ----
// phase 1: per-block degree sums
__global__ void __launch_bounds__(256) k_degsum() {
    __shared__ int sh[256];
    int tid = threadIdx.x;
    int i = blockIdx.x * 256 + tid;
    sh[tid] = (i < NN) ? g_deg[i] : 0;
    __syncthreads();
#pragma unroll
    for (int off = 128; off > 0; off >>= 1) {
        if (tid < off) sh[tid] += sh[tid + off];
        __syncthreads();
    }
    if (tid == 0) g_bsum[blockIdx.x] = sh[0];
}
// phase 2: scan the 196 block sums (one tiny block)
__global__ void __launch_bounds__(256) k_scanb() {
    __shared__ int sh[256];
    int tid = threadIdx.x;
    sh[tid] = (tid < NB) ? g_bsum[tid] : 0;
    __syncthreads();
#pragma unroll
    for (int off = 1; off < 256; off <<= 1) {
        int v = sh[tid];
        int a = (tid >= off) ? sh[tid - off] : 0;
        __syncthreads();
        sh[tid] = v + a;
        __syncthreads();
    }
    if (tid < NB) g_boff[tid] = (tid == 0) ? 0 : sh[tid - 1];
    if (tid == 0) g_rowptr[NN] = sh[NB - 1];
}
// phase 3: in-block scan + global offset; also writes g_cnt and g_dis
__global__ void __launch_bounds__(256) k_rowptr() {
    __shared__ int sh[256];
    int tid = threadIdx.x;
    int i = blockIdx.x * 256 + tid;
    int d = (i < NN) ? g_deg[i] : 0;
    sh[tid] = d;
    __syncthreads();
#pragma unroll
    for (int off = 1; off < 256; off <<= 1) {
        int v = sh[tid];
        int a = (tid >= off) ? sh[tid - off] : 0;
        __syncthreads();
        sh[tid] = v + a;
        __syncthreads();
    }
    if (i < NN) {
        int excl = sh[tid] - d + g_boff[blockIdx.x];
        g_rowptr[i] = excl;
        g_cnt[i]    = excl;
        g_dis[i]    = rsqrtf((float)d + 1.0f);
    }
}
__global__ void k_fill(const void* __restrict__ ei) {
    int e = blockIdx.x * blockDim.x + threadIdx.x;
    if (e < NE) {
        int s = load_edge(ei, e);
        int d = load_edge(ei, (long long)NE + e);
        if ((unsigned)s < (unsigned)NN && (unsigned)d < (unsigned)NN) {
            int pos = atomicAdd(&g_cnt[d], 1);
            if ((unsigned)pos < (unsigned)NE) g_col[pos] = s;
        }
    }
}

// ---------------- GEMM 128x128: g_h[row][c] = (SRC[row] . W[:,c]) * dis[row] ----------------
// block: 256 threads, tile 64 rows x 128 cols, thread: 8 rows x 4 cols (R14 config).
// Two 64-wide K chunks; static shared exactly 48KB.
__global__ void __launch_bounds__(256) k_gemm128(const float* __restrict__ X,
                                                 const float* __restrict__ W,
                                                 int use_gx) {
    __shared__ float Ws[64][HIDC];   // 32KB
    __shared__ float Xs[64][64];     // 16KB
    const float* src = use_gx ? (const float*)g_x : X;

    int tid  = threadIdx.x;
    int row0 = blockIdx.x * 64;
    int cg = tid & 31;   // cols cg*4 .. cg*4+3
    int rg = tid >> 5;   // rows rg*8 .. rg*8+7 (uniform within warp -> Xs broadcast)

    float4 acc[8];
#pragma unroll
    for (int r = 0; r < 8; r++) acc[r] = make_float4(0.f, 0.f, 0.f, 0.f);

#pragma unroll 1
    for (int kc = 0; kc < 2; kc++) {
        const float* Wsrc = W + kc * 64 * HIDC;
        for (int i = tid * 4; i < 64 * HIDC; i += 256 * 4)
            *(float4*)(&Ws[0][0] + i) = *(const float4*)(Wsrc + i);
        for (int i = tid; i < 64 * 16; i += 256) {
            int r  = i >> 4;
            int kg = (i & 15) * 4;
            int row = row0 + r;
            float4 v = make_float4(0.f, 0.f, 0.f, 0.f);
            if (row < NN) v = *(const float4*)&src[(size_t)row * HIDC + kc * 64 + kg];
            *(float4*)&Xs[r][kg] = v;
        }
        __syncthreads();

        for (int k = 0; k < 64; k += 4) {
            float4 xv[8];
#pragma unroll
            for (int r = 0; r < 8; r++)
                xv[r] = *(float4*)&Xs[rg * 8 + r][k];
#pragma unroll
            for (int kk = 0; kk < 4; kk++) {
                float4 w4 = *(float4*)&Ws[k + kk][cg * 4];
#pragma unroll
                for (int r = 0; r < 8; r++) {
                    float xs = (kk == 0) ? xv[r].x : (kk == 1) ? xv[r].y
                             : (kk == 2) ? xv[r].z : xv[r].w;
                    acc[r].x = fmaf(xs, w4.x, acc[r].x);
                    acc[r].y = fmaf(xs, w4.y, acc[r].y);
                    acc[r].z = fmaf(xs, w4.z, acc[r].z);
                    acc[r].w = fmaf(xs, w4.w, acc[r].w);
                }
            }
        }
        __syncthreads();
    }

#pragma unroll
    for (int r = 0; r < 8; r++) {
        int row = row0 + rg * 8 + r;
        if (row < NN) {
            float d = g_dis[row];
            float4 o = make_float4(acc[r].x * d, acc[r].y * d, acc[r].z * d, acc[r].w * d);
            *(float4*)&g_h[(size_t)row * HIDC + cg * 4] = o;
        }
    }
}

// ---------------- GEMM 128x32 (final layer): g_h2 = (g_x @ W2) * dis ----------------
__global__ void __launch_bounds__(256) k_gemm32(const float* __restrict__ W2) {
    __shared__ float Ws[HIDC * NOUT];  // 16KB
    int tid = threadIdx.x;
    for (int i = tid * 4; i < HIDC * NOUT; i += 256 * 4)
        *(float4*)&Ws[i] = *(const float4*)&W2[i];
    __syncthreads();

    int lane = tid & 31, w = tid >> 5;
    int row = blockIdx.x * 8 + w;
    if (row >= NN) return;
    const float* xr = g_x + (size_t)row * HIDC;
    float acc = 0.f;
#pragma unroll
    for (int k = 0; k < HIDC; k += 4) {
        float4 x4 = *(const float4*)&xr[k];  // uniform across warp
        acc = fmaf(x4.x, Ws[(k + 0) * NOUT + lane], acc);
        acc = fmaf(x4.y, Ws[(k + 1) * NOUT + lane], acc);
        acc = fmaf(x4.z, Ws[(k + 2) * NOUT + lane], acc);
        acc = fmaf(x4.w, Ws[(k + 3) * NOUT + lane], acc);
    }
    g_h2[(size_t)row * NOUT + lane] = acc * g_dis[row];
}

// ---------------- CSR aggregation + fused BN partial reduction ----------------
// warp per node, float4 per lane; g_agg = dis*(self + neighbor sum) + b.
// Also accumulates per-channel sum / sum-of-squares into g_bnsum/g_bnsq[layer].
// NN*32 == 1.6M threads == exactly 6250 blocks of 256.
__global__ void __launch_bounds__(256) k_aggbn(const float* __restrict__ b, int layer) {
    __shared__ float s_sum[HIDC], s_sq[HIDC];
    int tid  = threadIdx.x;
    if (tid < HIDC) { s_sum[tid] = 0.f; s_sq[tid] = 0.f; }
    __syncthreads();

    int node = (blockIdx.x * 256 + tid) >> 5;
    int lane = tid & 31;
    const float4* hs4 = (const float4*)g_h;
    float4 acc = hs4[(size_t)node * 32 + lane];   // self term (hs already *dis[src])
    int e0 = g_rowptr[node], e1 = g_rowptr[node + 1];
    int e = e0;
    for (; e + 1 < e1; e += 2) {
        int s0 = g_col[e], s1 = g_col[e + 1];
        float4 v0 = hs4[(size_t)s0 * 32 + lane];
        float4 v1 = hs4[(size_t)s1 * 32 + lane];
        acc.x += v0.x + v1.x; acc.y += v0.y + v1.y;
        acc.z += v0.z + v1.z; acc.w += v0.w + v1.w;
    }
    if (e < e1) {
        int s = g_col[e];
        float4 v = hs4[(size_t)s * 32 + lane];
        acc.x += v.x; acc.y += v.y; acc.z += v.z; acc.w += v.w;
    }
    float d = g_dis[node];
    float4 bb = *(const float4*)&b[lane * 4];
    float4 o = make_float4(acc.x * d + bb.x, acc.y * d + bb.y,
                           acc.z * d + bb.z, acc.w * d + bb.w);
    ((float4*)g_agg)[(size_t)node * 32 + lane] = o;

    int c = lane * 4;
    atomicAdd(&s_sum[c + 0], o.x);  atomicAdd(&s_sq[c + 0], o.x * o.x);
    atomicAdd(&s_sum[c + 1], o.y);  atomicAdd(&s_sq[c + 1], o.y * o.y);
    atomicAdd(&s_sum[c + 2], o.z);  atomicAdd(&s_sq[c + 2], o.z * o.z);
    atomicAdd(&s_sum[c + 3], o.w);  atomicAdd(&s_sq[c + 3], o.w * o.w);
    __syncthreads();
    if (tid < HIDC) {
        atomicAdd(&g_bnsum[layer * HIDC + tid], s_sum[tid]);
        atomicAdd(&g_bnsq [layer * HIDC + tid], s_sq[tid]);
    }
}

// ---------------- BN apply (stats finalized per block) + ReLU + residual ----------------
// g_x = relu(g_agg*scale + shift) + (use_gx ? g_x : X)
__global__ void __launch_bounds__(256) k_bnapply(const float* __restrict__ X,
                                                 const float* __restrict__ g,
                                                 const float* __restrict__ be,
                                                 int layer, int use_gx) {
    __shared__ float s_scale[HIDC], s_shift[HIDC];
    int tid = threadIdx.x;
    if (tid < HIDC) {
        float mu  = g_bnsum[layer * HIDC + tid] * (1.0f / (float)NN);
        float var = g_bnsq [layer * HIDC + tid] * (1.0f / (float)NN) - mu * mu;
        float a = rsqrtf(var + 1e-5f) * g[tid];
        s_scale[tid] = a;
        s_shift[tid] = be[tid] - mu * a;
    }
    __syncthreads();

    int idx = blockIdx.x * 256 + tid;   // exactly NN*32 float4 groups
    const float4* xin = use_gx ? (const float4*)g_x : (const float4*)X;
    int cg = (idx & 31) * 4;
    float4 v  = ((const float4*)g_agg)[idx];
    float4 xi = xin[idx];
    float4 a  = *(float4*)&s_scale[cg];
    float4 sh = *(float4*)&s_shift[cg];
    float4 o;
    o.x = fmaxf(fmaf(v.x, a.x, sh.x), 0.f) + xi.x;
    o.y = fmaxf(fmaf(v.y, a.y, sh.y), 0.f) + xi.y;
    o.z = fmaxf(fmaf(v.z, a.z, sh.z), 0.f) + xi.z;
    o.w = fmaxf(fmaf(v.w, a.w, sh.w), 0.f) + xi.w;
    ((float4*)g_x)[idx] = o;
}

// ---------------- final aggregation + log_softmax (warp per node, lane = class) ----------------
__global__ void __launch_bounds__(256) k_aggout(const float* __restrict__ b2,
                                                float* __restrict__ OUT) {
    int node = (blockIdx.x * 256 + threadIdx.x) >> 5;
    int lane = threadIdx.x & 31;
    if (node >= NN) return;
    float acc = g_h2[(size_t)node * NOUT + lane];
    int e0 = g_rowptr[node], e1 = g_rowptr[node + 1];
    for (int e = e0; e < e1; e++) {
        int s = g_col[e];
        acc += g_h2[(size_t)s * NOUT + lane];
    }
    float z = acc * g_dis[node] + b2[lane];
    float m = z;
#pragma unroll
    for (int o = 16; o > 0; o >>= 1) m = fmaxf(m, __shfl_xor_sync(0xffffffffu, m, o));
    float ex = expf(z - m);
    float sm = ex;
#pragma unroll
    for (int o = 16; o > 0; o >>= 1) sm += __shfl_xor_sync(0xffffffffu, sm, o);
    OUT[(size_t)node * NOUT + lane] = z - m - logf(sm);
}

// ---------------- host launch: kernel launches ONLY ----------------
extern "C" void kernel_launch(void* const* d_in, const int* in_sizes, int n_in,
                              void* d_out, int out_size) {
    const float* x   = (const float*)d_in[0];
    const void*  ei  = d_in[1];
    const float* W0  = (const float*)d_in[2];
    const float* b0  = (const float*)d_in[3];
    const float* g0  = (const float*)d_in[4];
    const float* be0 = (const float*)d_in[5];
    const float* W1  = (const float*)d_in[6];
    const float* b1  = (const float*)d_in[7];
    const float* g1  = (const float*)d_in[8];
    const float* be1 = (const float*)d_in[9];
    const float* W2  = (const float*)d_in[10];
    const float* b2  = (const float*)d_in[11];
    float*       out = (float*)d_out;

    // ---- dtype detect + graph / degree / CSR build (multi-block scan) ----
    k_detect<<<1, 1024>>>((const unsigned int*)ei);
    k_zero<<<(NN + 255) / 256, 256>>>();
    k_deg<<<(NE + 255) / 256, 256>>>(ei);
    k_degsum<<<NB, 256>>>();
    k_scanb<<<1, 256>>>();
    k_rowptr<<<NB, 256>>>();
    k_fill<<<(NE + 255) / 256, 256>>>(ei);

    const int GB = (NN + 63) / 64;        // gemm128 blocks (782)
    const int WB = (NN * 32) / 256;       // warp-per-node blocks (6250, exact)

    // ---- layer 0 ----
    k_gemm128<<<GB, 256>>>(x, W0, 0);
    k_aggbn<<<WB, 256>>>(b0, 0);
    k_bnapply<<<WB, 256>>>(x, g0, be0, 0, 0);

    // ---- layer 1 ----
    k_gemm128<<<GB, 256>>>(x, W1, 1);
    k_aggbn<<<WB, 256>>>(b1, 1);
    k_bnapply<<<WB, 256>>>(x, g1, be1, 1, 1);

    // ---- final layer + log_softmax ----
    k_gemm32<<<(NN + 7) / 8, 256>>>(W2);
    k_aggout<<<WB, 256>>>(b2, out);
}

// round 17
// speedup vs baseline: 1.3839x; 1.0007x over previous
#include <cuda_runtime.h>
#include <math.h>

#define NN   50000
#define NE   800000
#define HIDC 128
#define NOUT 32
#define NB   196   // ceil(NN/256) blocks for the scan phases

// ---------------- scratch (device globals; no allocation allowed) ----------------
__device__ __align__(16) float g_h   [NN * HIDC];   // hs = (x@W)*dis[row]
__device__ __align__(16) float g_agg [NN * HIDC];   // aggregated pre-BN
__device__ __align__(16) float g_x   [NN * HIDC];   // running features (post residual)
__device__ __align__(16) float g_h2  [NN * NOUT];   // final-layer hs
__device__ __align__(16) float g_dis [NN];
__device__ int   g_deg   [NN];
__device__ int   g_rowptr[NN + 1];
__device__ int   g_cnt   [NN];
__device__ int   g_col   [NE];
__device__ int   g_bsum  [NB];
__device__ int   g_boff  [NB];
__device__ int   g_is64;
__device__ __align__(16) float g_bnsum[2 * HIDC];   // per-layer BN sum
__device__ __align__(16) float g_bnsq [2 * HIDC];   // per-layer BN sum-of-squares

// ---------------- dtype detection for edge_index (int32 vs int64) ----------------
__global__ void k_detect(const unsigned int* __restrict__ w) {
    __shared__ int any_nz;
    if (threadIdx.x == 0) any_nz = 0;
    __syncthreads();
    unsigned int v = w[2 * threadIdx.x + 1];   // tid in [0,1024)
    if (v != 0u) atomicOr(&any_nz, 1);
    __syncthreads();
    if (threadIdx.x == 0) g_is64 = any_nz ? 0 : 1;
}

__device__ __forceinline__ int load_edge(const void* ei, long long idx) {
    if (g_is64) return (int)((const long long*)ei)[idx];
    return ((const int*)ei)[idx];
}

// ---------------- setup kernels ----------------
// zero degree + both layers' BN accumulators (must re-zero every launch)
__global__ void k_zero() {
    int i = blockIdx.x * blockDim.x + threadIdx.x;
    if (i < NN) g_deg[i] = 0;
    if (i < 2 * HIDC) { g_bnsum[i] = 0.f; g_bnsq[i] = 0.f; }
}
__global__ void k_deg(const void* __restrict__ ei) {
    int e = blockIdx.x * blockDim.x + threadIdx.x;
    if (e < NE) {
        int d = load_edge(ei, (long long)NE + e);
        if ((unsigned)d < (unsigned)NN)
            atomicAdd(&g_deg[d], 1);
    }
}

// ---- multi-block exclusive scan of g_deg -> g_rowptr (3 phases) ----
// phase 1: per-block degree sums
__global__ void __launch_bounds__(256) k_degsum() {
    __shared__ int sh[256];
    int tid = threadIdx.x;
    int i = blockIdx.x * 256 + tid;
    sh[tid] = (i < NN) ? g_deg[i] : 0;
    __syncthreads();
#pragma unroll
    for (int off = 128; off > 0; off >>= 1) {
        if (tid < off) sh[tid] += sh[tid + off];
        __syncthreads();
    }
    if (tid == 0) g_bsum[blockIdx.x] = sh[0];
}
// phase 2: scan the 196 block sums (one tiny block)
__global__ void __launch_bounds__(256) k_scanb() {
    __shared__ int sh[256];
    int tid = threadIdx.x;
    sh[tid] = (tid < NB) ? g_bsum[tid] : 0;
    __syncthreads();
#pragma unroll
    for (int off = 1; off < 256; off <<= 1) {
        int v = sh[tid];
        int a = (tid >= off) ? sh[tid - off] : 0;
        __syncthreads();
        sh[tid] = v + a;
        __syncthreads();
    }
    if (tid < NB) g_boff[tid] = (tid == 0) ? 0 : sh[tid - 1];
    if (tid == 0) g_rowptr[NN] = sh[NB - 1];
}
// phase 3: in-block scan + global offset; also writes g_cnt and g_dis
__global__ void __launch_bounds__(256) k_rowptr() {
    __shared__ int sh[256];
    int tid = threadIdx.x;
    int i = blockIdx.x * 256 + tid;
    int d = (i < NN) ? g_deg[i] : 0;
    sh[tid] = d;
    __syncthreads();
#pragma unroll
    for (int off = 1; off < 256; off <<= 1) {
        int v = sh[tid];
        int a = (tid >= off) ? sh[tid - off] : 0;
        __syncthreads();
        sh[tid] = v + a;
        __syncthreads();
    }
    if (i < NN) {
        int excl = sh[tid] - d + g_boff[blockIdx.x];
        g_rowptr[i] = excl;
        g_cnt[i]    = excl;
        g_dis[i]    = rsqrtf((float)d + 1.0f);
    }
}
__global__ void k_fill(const void* __restrict__ ei) {
    int e = blockIdx.x * blockDim.x + threadIdx.x;
    if (e < NE) {
        int s = load_edge(ei, e);
        int d = load_edge(ei, (long long)NE + e);
        if ((unsigned)s < (unsigned)NN && (unsigned)d < (unsigned)NN) {
            int pos = atomicAdd(&g_cnt[d], 1);
            if ((unsigned)pos < (unsigned)NE) g_col[pos] = s;
        }
    }
}

// ---------------- GEMM 128x128: g_h[row][c] = (SRC[row] . W[:,c]) * dis[row] ----------------
// block: 256 threads, tile 64 rows x 128 cols, thread: 8 rows x 4 cols (R14 config).
// Two 64-wide K chunks; static shared exactly 48KB.
__global__ void __launch_bounds__(256) k_gemm128(const float* __restrict__ X,
                                                 const float* __restrict__ W,
                                                 int use_gx) {
    __shared__ float Ws[64][HIDC];   // 32KB
    __shared__ float Xs[64][64];     // 16KB
    const float* src = use_gx ? (const float*)g_x : X;

    int tid  = threadIdx.x;
    int row0 = blockIdx.x * 64;
    int cg = tid & 31;   // cols cg*4 .. cg*4+3
    int rg = tid >> 5;   // rows rg*8 .. rg*8+7 (uniform within warp -> Xs broadcast)

    float4 acc[8];
#pragma unroll
    for (int r = 0; r < 8; r++) acc[r] = make_float4(0.f, 0.f, 0.f, 0.f);

#pragma unroll 1
    for (int kc = 0; kc < 2; kc++) {
        const float* Wsrc = W + kc * 64 * HIDC;
        for (int i = tid * 4; i < 64 * HIDC; i += 256 * 4)
            *(float4*)(&Ws[0][0] + i) = *(const float4*)(Wsrc + i);
        for (int i = tid; i < 64 * 16; i += 256) {
            int r  = i >> 4;
            int kg = (i & 15) * 4;
            int row = row0 + r;
            float4 v = make_float4(0.f, 0.f, 0.f, 0.f);
            if (row < NN) v = *(const float4*)&src[(size_t)row * HIDC + kc * 64 + kg];
            *(float4*)&Xs[r][kg] = v;
        }
        __syncthreads();

        for (int k = 0; k < 64; k += 4) {
            float4 xv[8];
#pragma unroll
            for (int r = 0; r < 8; r++)
                xv[r] = *(float4*)&Xs[rg * 8 + r][k];
#pragma unroll
            for (int kk = 0; kk < 4; kk++) {
                float4 w4 = *(float4*)&Ws[k + kk][cg * 4];
#pragma unroll
                for (int r = 0; r < 8; r++) {
                    float xs = (kk == 0) ? xv[r].x : (kk == 1) ? xv[r].y
                             : (kk == 2) ? xv[r].z : xv[r].w;
                    acc[r].x = fmaf(xs, w4.x, acc[r].x);
                    acc[r].y = fmaf(xs, w4.y, acc[r].y);
                    acc[r].z = fmaf(xs, w4.z, acc[r].z);
                    acc[r].w = fmaf(xs, w4.w, acc[r].w);
                }
            }
        }
        __syncthreads();
    }

#pragma unroll
    for (int r = 0; r < 8; r++) {
        int row = row0 + rg * 8 + r;
        if (row < NN) {
            float d = g_dis[row];
            float4 o = make_float4(acc[r].x * d, acc[r].y * d, acc[r].z * d, acc[r].w * d);
            *(float4*)&g_h[(size_t)row * HIDC + cg * 4] = o;
        }
    }
}

// ---------------- GEMM 128x32 (final layer): g_h2 = (g_x @ W2) * dis ----------------
__global__ void __launch_bounds__(256) k_gemm32(const float* __restrict__ W2) {
    __shared__ float Ws[HIDC * NOUT];  // 16KB
    int tid = threadIdx.x;
    for (int i = tid * 4; i < HIDC * NOUT; i += 256 * 4)
        *(float4*)&Ws[i] = *(const float4*)&W2[i];
    __syncthreads();

    int lane = tid & 31, w = tid >> 5;
    int row = blockIdx.x * 8 + w;
    if (row >= NN) return;
    const float* xr = g_x + (size_t)row * HIDC;
    float acc = 0.f;
#pragma unroll
    for (int k = 0; k < HIDC; k += 4) {
        float4 x4 = *(const float4*)&xr[k];  // uniform across warp
        acc = fmaf(x4.x, Ws[(k + 0) * NOUT + lane], acc);
        acc = fmaf(x4.y, Ws[(k + 1) * NOUT + lane], acc);
        acc = fmaf(x4.z, Ws[(k + 2) * NOUT + lane], acc);
        acc = fmaf(x4.w, Ws[(k + 3) * NOUT + lane], acc);
    }
    g_h2[(size_t)row * NOUT + lane] = acc * g_dis[row];
}

// ---------------- CSR aggregation + fused BN partial reduction ----------------
// warp per node, float4 per lane; g_agg = dis*(self + neighbor sum) + b.
// Also accumulates per-channel sum / sum-of-squares into g_bnsum/g_bnsq[layer].
// NN*32 == 1.6M threads == exactly 6250 blocks of 256.
__global__ void __launch_bounds__(256) k_aggbn(const float* __restrict__ b, int layer) {
    __shared__ float s_sum[HIDC], s_sq[HIDC];
    int tid  = threadIdx.x;
    if (tid < HIDC) { s_sum[tid] = 0.f; s_sq[tid] = 0.f; }
    __syncthreads();

    int node = (blockIdx.x * 256 + tid) >> 5;
    int lane = tid & 31;
    const float4* hs4 = (const float4*)g_h;
    float4 acc = hs4[(size_t)node * 32 + lane];   // self term (hs already *dis[src])
    int e0 = g_rowptr[node], e1 = g_rowptr[node + 1];
    int e = e0;
    for (; e + 1 < e1; e += 2) {
        int s0 = g_col[e], s1 = g_col[e + 1];
        float4 v0 = hs4[(size_t)s0 * 32 + lane];
        float4 v1 = hs4[(size_t)s1 * 32 + lane];
        acc.x += v0.x + v1.x; acc.y += v0.y + v1.y;
        acc.z += v0.z + v1.z; acc.w += v0.w + v1.w;
    }
    if (e < e1) {
        int s = g_col[e];
        float4 v = hs4[(size_t)s * 32 + lane];
        acc.x += v.x; acc.y += v.y; acc.z += v.z; acc.w += v.w;
    }
    float d = g_dis[node];
    float4 bb = *(const float4*)&b[lane * 4];
    float4 o = make_float4(acc.x * d + bb.x, acc.y * d + bb.y,
                           acc.z * d + bb.z, acc.w * d + bb.w);
    ((float4*)g_agg)[(size_t)node * 32 + lane] = o;

    int c = lane * 4;
    atomicAdd(&s_sum[c + 0], o.x);  atomicAdd(&s_sq[c + 0], o.x * o.x);
    atomicAdd(&s_sum[c + 1], o.y);  atomicAdd(&s_sq[c + 1], o.y * o.y);
    atomicAdd(&s_sum[c + 2], o.z);  atomicAdd(&s_sq[c + 2], o.z * o.z);
    atomicAdd(&s_sum[c + 3], o.w);  atomicAdd(&s_sq[c + 3], o.w * o.w);
    __syncthreads();
    if (tid < HIDC) {
        atomicAdd(&g_bnsum[layer * HIDC + tid], s_sum[tid]);
        atomicAdd(&g_bnsq [layer * HIDC + tid], s_sq[tid]);
    }
}

// ---------------- BN apply (stats finalized per block) + ReLU + residual ----------------
// g_x = relu(g_agg*scale + shift) + (use_gx ? g_x : X)
__global__ void __launch_bounds__(256) k_bnapply(const float* __restrict__ X,
                                                 const float* __restrict__ g,
                                                 const float* __restrict__ be,
                                                 int layer, int use_gx) {
    __shared__ float s_scale[HIDC], s_shift[HIDC];
    int tid = threadIdx.x;
    if (tid < HIDC) {
        float mu  = g_bnsum[layer * HIDC + tid] * (1.0f / (float)NN);
        float var = g_bnsq [layer * HIDC + tid] * (1.0f / (float)NN) - mu * mu;
        float a = rsqrtf(var + 1e-5f) * g[tid];
        s_scale[tid] = a;
        s_shift[tid] = be[tid] - mu * a;
    }
    __syncthreads();

    int idx = blockIdx.x * 256 + tid;   // exactly NN*32 float4 groups
    const float4* xin = use_gx ? (const float4*)g_x : (const float4*)X;
    int cg = (idx & 31) * 4;
    float4 v  = ((const float4*)g_agg)[idx];
    float4 xi = xin[idx];
    float4 a  = *(float4*)&s_scale[cg];
    float4 sh = *(float4*)&s_shift[cg];
    float4 o;
    o.x = fmaxf(fmaf(v.x, a.x, sh.x), 0.f) + xi.x;
    o.y = fmaxf(fmaf(v.y, a.y, sh.y), 0.f) + xi.y;
    o.z = fmaxf(fmaf(v.z, a.z, sh.z), 0.f) + xi.z;
    o.w = fmaxf(fmaf(v.w, a.w, sh.w), 0.f) + xi.w;
    ((float4*)g_x)[idx] = o;
}

// ---------------- final aggregation + log_softmax (warp per node, lane = class) ----------------
__global__ void __launch_bounds__(256) k_aggout(const float* __restrict__ b2,
                                                float* __restrict__ OUT) {
    int node = (blockIdx.x * 256 + threadIdx.x) >> 5;
    int lane = threadIdx.x & 31;
    if (node >= NN) return;
    float acc = g_h2[(size_t)node * NOUT + lane];
    int e0 = g_rowptr[node], e1 = g_rowptr[node + 1];
    for (int e = e0; e < e1; e++) {
        int s = g_col[e];
        acc += g_h2[(size_t)s * NOUT + lane];
    }
    float z = acc * g_dis[node] + b2[lane];
    float m = z;
#pragma unroll
    for (int o = 16; o > 0; o >>= 1) m = fmaxf(m, __shfl_xor_sync(0xffffffffu, m, o));
    float ex = expf(z - m);
    float sm = ex;
#pragma unroll
    for (int o = 16; o > 0; o >>= 1) sm += __shfl_xor_sync(0xffffffffu, sm, o);
    OUT[(size_t)node * NOUT + lane] = z - m - logf(sm);
}

// ---------------- host launch: kernel launches ONLY ----------------
extern "C" void kernel_launch(void* const* d_in, const int* in_sizes, int n_in,
                              void* d_out, int out_size) {
    const float* x   = (const float*)d_in[0];
    const void*  ei  = d_in[1];
    const float* W0  = (const float*)d_in[2];
    const float* b0  = (const float*)d_in[3];
    const float* g0  = (const float*)d_in[4];
    const float* be0 = (const float*)d_in[5];
    const float* W1  = (const float*)d_in[6];
    const float* b1  = (const float*)d_in[7];
    const float* g1  = (const float*)d_in[8];
    const float* be1 = (const float*)d_in[9];
    const float* W2  = (const float*)d_in[10];
    const float* b2  = (const float*)d_in[11];
    float*       out = (float*)d_out;

    // ---- dtype detect + graph / degree / CSR build (multi-block scan) ----
    k_detect<<<1, 1024>>>((const unsigned int*)ei);
    k_zero<<<(NN + 255) / 256, 256>>>();
    k_deg<<<(NE + 255) / 256, 256>>>(ei);
    k_degsum<<<NB, 256>>>();
    k_scanb<<<1, 256>>>();
    k_rowptr<<<NB, 256>>>();
    k_fill<<<(NE + 255) / 256, 256>>>(ei);

    const int GB = (NN + 63) / 64;        // gemm128 blocks (782)
    const int WB = (NN * 32) / 256;       // warp-per-node blocks (6250, exact)

    // ---- layer 0 ----
    k_gemm128<<<GB, 256>>>(x, W0, 0);
    k_aggbn<<<WB, 256>>>(b0, 0);
    k_bnapply<<<WB, 256>>>(x, g0, be0, 0, 0);

    // ---- layer 1 ----
    k_gemm128<<<GB, 256>>>(x, W1, 1);
    k_aggbn<<<WB, 256>>>(b1, 1);
    k_bnapply<<<WB, 256>>>(x, g1, be1, 1, 1);

    // ---- final layer + log_softmax ----
    k_gemm32<<<(NN + 7) / 8, 256>>>(W2);
    k_aggout<<<WB, 256>>>(b2, out);
}